// round 11
// baseline (speedup 1.0000x reference)
#include <cuda_runtime.h>
#include <cstdint>

// Problem constants
#define B 256
#define T 512
#define H 512
#define O 2

// d_out layout (floats): out, hidden, net_units, read_out_units
#define HID_OFF (B * O)
#define NET_OFF (HID_OFF + B * H)
#define RO_OFF  (NET_OFF + B * T * H)

#define CLUSTER   8
#define NCTA      128          // 16 clusters x 8 CTAs
#define NTHREADS  512
#define HSTRIDE   516          // h row stride in floats (bank skew)

// smem layout (floats):
//   W2  : 256 kp x 64 float2 = 32768 floats  (128 KB)
//   hb  : 2 bufs x 16 rows x HSTRIDE         (64.5 KB)
//   Rs  : 3 x 128 x 8 partials               (12 KB)
#define W2_FLOATS  (256 * 64 * 2)
#define HB_FLOATS  (2 * 16 * HSTRIDE)
#define RS_FLOATS  (3 * 128 * 8)
#define SMEM_BYTES ((W2_FLOATS + HB_FLOATS + RS_FLOATS) * 4)   // 209,408 B

#define CLUSTER_SYNC() do { \
    asm volatile("barrier.cluster.arrive.aligned;" ::: "memory"); \
    asm volatile("barrier.cluster.wait.aligned;"   ::: "memory"); \
} while (0)

__device__ __forceinline__ uint32_t smem_u32(const void* p) {
    return (uint32_t)__cvta_generic_to_shared(p);
}
__device__ __forceinline__ uint32_t mapa_rank(uint32_t laddr, uint32_t rank) {
    uint32_t ra;
    asm("mapa.shared::cluster.u32 %0, %1, %2;" : "=r"(ra) : "r"(laddr), "r"(rank));
    return ra;
}
__device__ __forceinline__ void st_remote_v4(uint32_t ra, float4 v) {
    asm volatile("st.shared::cluster.v4.f32 [%0], {%1,%2,%3,%4};"
                 :: "r"(ra), "f"(v.x), "f"(v.y), "f"(v.z), "f"(v.w) : "memory");
}

// ---------------------------------------------------------------------------
// Pre-pass: net[b,t,j] = input.W_in + b_in + b_hh + sigma*noise
// ---------------------------------------------------------------------------
__global__ __launch_bounds__(128) void pre_kernel(
    const float* __restrict__ input, const float* __restrict__ sigma,
    const float* __restrict__ noise, const float* __restrict__ W_in,
    const float* __restrict__ b_in,  const float* __restrict__ b_hh,
    float* __restrict__ net)
{
    const int b  = blockIdx.x;
    const int t0 = blockIdx.y * 8;
    const int j  = threadIdx.x * 4;

    float4 wi0 = *(const float4*)(W_in + j * 2);
    float4 wi1 = *(const float4*)(W_in + j * 2 + 4);
    float4 bi  = *(const float4*)(b_in + j);
    float4 bh  = *(const float4*)(b_hh + j);
    float4 c;
    c.x = bi.x + bh.x; c.y = bi.y + bh.y; c.z = bi.z + bh.z; c.w = bi.w + bh.w;
    const float sn = sigma[0];

    #pragma unroll
    for (int tt = 0; tt < 8; tt++) {
        const int t = t0 + tt;
        const size_t bt = (size_t)b * T + t;
        const float in0 = input[bt * 2 + 0];
        const float in1 = input[bt * 2 + 1];
        float4 nz = *(const float4*)(noise + bt * H + j);
        float4 r;
        r.x = in0 * wi0.x + in1 * wi0.y + c.x + sn * nz.x;
        r.y = in0 * wi0.z + in1 * wi0.w + c.y + sn * nz.y;
        r.z = in0 * wi1.x + in1 * wi1.y + c.z + sn * nz.z;
        r.w = in0 * wi1.z + in1 * wi1.w + c.w + sn * nz.w;
        *(float4*)(net + bt * H + j) = r;
    }
}

// ---------------------------------------------------------------------------
// Cluster recurrence. Cluster = 8 CTAs over one 16-batch-row group.
// CTA rank owns output cols [rank*64, rank*64+64).
// 512 threads: kq = tid>>7 (k-quarter), s = tid&127, row = s>>3, tn = s&7
// -> thread computes 8 cols (j0+8tn..+7) for row b0+row over 128 k (64 kp).
// ---------------------------------------------------------------------------
__global__ __launch_bounds__(NTHREADS, 1) __cluster_dims__(CLUSTER, 1, 1)
void rnn_cluster_kernel(
    const float* __restrict__ W_hh,   // [H,H]
    float*       __restrict__ net)    // [B,T,H]
{
    extern __shared__ float smem[];
    float* W2 = smem;                          // k-pair interleaved W tile
    float* hb = smem + W2_FLOATS;              // hb[buf][row][HSTRIDE]
    float* Rs = smem + W2_FLOATS + HB_FLOATS;  // partials

    const int tid  = threadIdx.x;
    const int rank = blockIdx.x & 7;           // == cluster_ctarank
    const int bg   = blockIdx.x >> 3;          // 0..15
    const int b0   = bg * 16;
    const int j0   = rank * 64;

    const int kq  = tid >> 7;                  // 0..3
    const int s   = tid & 127;
    const int row = s >> 3;                    // 0..15
    const int tn  = s & 7;                     // cols j0 + 8*tn .. +7

    // ---- Load W tile once: column c of output <- W_hh row (j0+c).
    // Storage: per kp (64 float2), chunk (i, tn) at float2 offset i*16+tn*2
    // holds k-pairs of cols (8tn+2i, 8tn+2i+1)  -> conflict-free LDS.128.
    {
        const int wc   = tid >> 3;             // 0..63 column
        const int wk0  = (tid & 7) * 64;       // 64 k per thread
        const int posc = (((wc & 7) >> 1) << 4) + ((wc >> 3) << 1) + (wc & 1);
        const float* src = W_hh + (size_t)(j0 + wc) * H + wk0;
        float2* W2f2 = (float2*)W2;
        #pragma unroll
        for (int c = 0; c < 64; c += 4) {
            float4 v = *(const float4*)(src + c);
            const int kp = (wk0 + c) >> 1;
            W2f2[(kp + 0) * 64 + posc] = make_float2(v.x, v.y);
            W2f2[(kp + 1) * 64 + posc] = make_float2(v.z, v.w);
        }
    }

    // ---- t = 0: h0 = relu(pre); stage into hb[0] locally ----
    if (kq == 0) {
        float* dst = net + ((size_t)(b0 + row) * T + 0) * H + j0 + tn * 8;
        float4 p0 = __ldcg((const float4*)dst);
        float4 p1 = __ldcg((const float4*)(dst + 4));
        p0.x = fmaxf(p0.x, 0.f); p0.y = fmaxf(p0.y, 0.f);
        p0.z = fmaxf(p0.z, 0.f); p0.w = fmaxf(p0.w, 0.f);
        p1.x = fmaxf(p1.x, 0.f); p1.y = fmaxf(p1.y, 0.f);
        p1.z = fmaxf(p1.z, 0.f); p1.w = fmaxf(p1.w, 0.f);
        *(float4*)dst       = p0;
        *(float4*)(dst + 4) = p1;
        float* hloc = hb + row * HSTRIDE + j0 + tn * 8;
        *(float4*)hloc       = p0;
        *(float4*)(hloc + 4) = p1;
    }
    __syncthreads();

    // ---- Broadcast own 16x64 slice of hb[buf] to the 7 peers ----
    // 256 float4 per tile x 7 ranks = 1792 remote stores over 512 threads.
    #define BROADCAST(bufbase)                                                  \
    do {                                                                        \
        for (int i = tid; i < 1792; i += NTHREADS) {                            \
            const int rr  = i >> 8;              /* 0..6 */                     \
            const int idx = i & 255;                                            \
            const int r_  = idx >> 4;            /* row */                      \
            const int c_  = (idx & 15) * 4;      /* col offset in tile */       \
            const uint32_t dstrank = (uint32_t)((rank + 1 + rr) & 7);           \
            const float* lp = (bufbase) + r_ * HSTRIDE + j0 + c_;               \
            float4 v = *(const float4*)lp;                                      \
            uint32_t ra = mapa_rank(smem_u32(lp), dstrank);                     \
            st_remote_v4(ra, v);                                                \
        }                                                                       \
    } while (0)

    BROADCAST(hb);

    for (int t = 1; t < T; t++) {
        CLUSTER_SYNC();                         // h(t-1) complete in all CTAs

        const float* hbR = hb + ((t - 1) & 1) * (16 * HSTRIDE);
        float*       hbW = hb + (t & 1) * (16 * HSTRIDE);

        // prefetch pre (independent of h)
        float4 pre0, pre1;
        float* dst = nullptr;
        if (kq == 0) {
            dst  = net + ((size_t)(b0 + row) * T + t) * H + j0 + tn * 8;
            pre0 = __ldcg((const float4*)dst);
            pre1 = __ldcg((const float4*)(dst + 4));
        }

        // ---- GEMM quarter: 64 kp, 8 cols per thread, paired-k FFMA2 ----
        unsigned long long a0 = 0, a1 = 0, a2 = 0, a3 = 0,
                           a4 = 0, a5 = 0, a6 = 0, a7 = 0;
        {
            const float* hrow = hbR + row * HSTRIDE;
            const int kp0 = kq * 64;
            #pragma unroll 4
            for (int kp = kp0; kp < kp0 + 64; kp++) {
                const unsigned long long hh =
                    *(const unsigned long long*)(hrow + 2 * kp);
                const ulonglong2* wb = (const ulonglong2*)(W2 + kp * 128 + tn * 4);
                ulonglong2 q0 = wb[0];
                ulonglong2 q1 = wb[8];
                ulonglong2 q2 = wb[16];
                ulonglong2 q3 = wb[24];
                asm("fma.rn.f32x2 %0, %1, %2, %0;" : "+l"(a0) : "l"(hh), "l"(q0.x));
                asm("fma.rn.f32x2 %0, %1, %2, %0;" : "+l"(a1) : "l"(hh), "l"(q0.y));
                asm("fma.rn.f32x2 %0, %1, %2, %0;" : "+l"(a2) : "l"(hh), "l"(q1.x));
                asm("fma.rn.f32x2 %0, %1, %2, %0;" : "+l"(a3) : "l"(hh), "l"(q1.y));
                asm("fma.rn.f32x2 %0, %1, %2, %0;" : "+l"(a4) : "l"(hh), "l"(q2.x));
                asm("fma.rn.f32x2 %0, %1, %2, %0;" : "+l"(a5) : "l"(hh), "l"(q2.y));
                asm("fma.rn.f32x2 %0, %1, %2, %0;" : "+l"(a6) : "l"(hh), "l"(q3.x));
                asm("fma.rn.f32x2 %0, %1, %2, %0;" : "+l"(a7) : "l"(hh), "l"(q3.y));
            }
        }
        float f[8];
        {
            float lo, hi;
            asm("mov.b64 {%0,%1}, %2;" : "=f"(lo), "=f"(hi) : "l"(a0)); f[0] = lo + hi;
            asm("mov.b64 {%0,%1}, %2;" : "=f"(lo), "=f"(hi) : "l"(a1)); f[1] = lo + hi;
            asm("mov.b64 {%0,%1}, %2;" : "=f"(lo), "=f"(hi) : "l"(a2)); f[2] = lo + hi;
            asm("mov.b64 {%0,%1}, %2;" : "=f"(lo), "=f"(hi) : "l"(a3)); f[3] = lo + hi;
            asm("mov.b64 {%0,%1}, %2;" : "=f"(lo), "=f"(hi) : "l"(a4)); f[4] = lo + hi;
            asm("mov.b64 {%0,%1}, %2;" : "=f"(lo), "=f"(hi) : "l"(a5)); f[5] = lo + hi;
            asm("mov.b64 {%0,%1}, %2;" : "=f"(lo), "=f"(hi) : "l"(a6)); f[6] = lo + hi;
            asm("mov.b64 {%0,%1}, %2;" : "=f"(lo), "=f"(hi) : "l"(a7)); f[7] = lo + hi;
        }

        if (kq != 0) {
            float* rp = Rs + ((size_t)(kq - 1) * 128 + s) * 8;
            *(float4*)(rp)     = make_float4(f[0], f[1], f[2], f[3]);
            *(float4*)(rp + 4) = make_float4(f[4], f[5], f[6], f[7]);
        }
        __syncthreads();                        // partials staged

        if (kq == 0) {
            const float* r0 = Rs + (size_t)s * 8;
            const float* r1 = Rs + (size_t)(128 + s) * 8;
            const float* r2 = Rs + (size_t)(256 + s) * 8;
            float4 o0, o1;
            o0.x = fmaxf(f[0] + r0[0] + r1[0] + r2[0] + pre0.x, 0.f);
            o0.y = fmaxf(f[1] + r0[1] + r1[1] + r2[1] + pre0.y, 0.f);
            o0.z = fmaxf(f[2] + r0[2] + r1[2] + r2[2] + pre0.z, 0.f);
            o0.w = fmaxf(f[3] + r0[3] + r1[3] + r2[3] + pre0.w, 0.f);
            o1.x = fmaxf(f[4] + r0[4] + r1[4] + r2[4] + pre1.x, 0.f);
            o1.y = fmaxf(f[5] + r0[5] + r1[5] + r2[5] + pre1.y, 0.f);
            o1.z = fmaxf(f[6] + r0[6] + r1[6] + r2[6] + pre1.z, 0.f);
            o1.w = fmaxf(f[7] + r0[7] + r1[7] + r2[7] + pre1.w, 0.f);
            *(float4*)dst       = o0;            // net output (off critical path)
            *(float4*)(dst + 4) = o1;
            float* hloc = hbW + row * HSTRIDE + j0 + tn * 8;
            *(float4*)hloc       = o0;           // local stage for broadcast
            *(float4*)(hloc + 4) = o1;
        }
        __syncthreads();                        // hbW slice ready

        BROADCAST(hbW);                         // push to 7 peers (fire & forget)
    }
    // final cluster sync so no CTA exits while peers' remote stores target it
    CLUSTER_SYNC();
    #undef BROADCAST
}

// ---------------------------------------------------------------------------
// Readout: ro[b,t,o] = net[b,t,:].W_fc[o,:] + b_fc[o]; out/hidden from t=T-1
// ---------------------------------------------------------------------------
__global__ __launch_bounds__(256) void readout_kernel(
    const float* __restrict__ net, const float* __restrict__ W_fc,
    const float* __restrict__ b_fc, float* __restrict__ ro,
    float* __restrict__ out, float* __restrict__ hidden)
{
    __shared__ float4 w0s[H / 4];
    __shared__ float4 w1s[H / 4];
    const int tid = threadIdx.x;
    if (tid < H / 4)            w0s[tid]         = ((const float4*)W_fc)[tid];
    else if (tid < 2 * (H / 4)) w1s[tid - H / 4] = ((const float4*)(W_fc + H))[tid - H / 4];
    __syncthreads();

    const int warp = tid >> 5, lane = tid & 31;
    const int bt = blockIdx.x * 8 + warp;
    const int b = bt / T, t = bt % T;

    const float4* rowp = (const float4*)(net + (size_t)bt * H);
    float a0 = 0.f, a1 = 0.f;
    float4 vals[4];
    #pragma unroll
    for (int i = 0; i < 4; i++) {
        float4 v  = rowp[lane + 32 * i];
        float4 w0 = w0s[lane + 32 * i];
        float4 w1 = w1s[lane + 32 * i];
        vals[i] = v;
        a0 += v.x * w0.x + v.y * w0.y + v.z * w0.z + v.w * w0.w;
        a1 += v.x * w1.x + v.y * w1.y + v.z * w1.z + v.w * w1.w;
    }
    #pragma unroll
    for (int sgap = 16; sgap > 0; sgap >>= 1) {
        a0 += __shfl_xor_sync(0xFFFFFFFFu, a0, sgap);
        a1 += __shfl_xor_sync(0xFFFFFFFFu, a1, sgap);
    }
    if (lane == 0) {
        ro[(size_t)bt * 2 + 0] = a0 + b_fc[0];
        ro[(size_t)bt * 2 + 1] = a1 + b_fc[1];
    }
    if (t == T - 1) {
        if (lane == 0) {
            out[b * 2 + 0] = a0 + b_fc[0];
            out[b * 2 + 1] = a1 + b_fc[1];
        }
        float4* hid = (float4*)(hidden + (size_t)b * H);
        #pragma unroll
        for (int i = 0; i < 4; i++) hid[lane + 32 * i] = vals[i];
    }
}

extern "C" void kernel_launch(void* const* d_in, const int* in_sizes, int n_in,
                              void* d_out, int out_size)
{
    const float* input = (const float*)d_in[0];
    const float* sigma = (const float*)d_in[1];
    const float* noise = (const float*)d_in[2];
    const float* W_in  = (const float*)d_in[3];
    const float* b_in  = (const float*)d_in[4];
    const float* W_hh  = (const float*)d_in[5];
    const float* b_hh  = (const float*)d_in[6];
    const float* W_fc  = (const float*)d_in[7];
    const float* b_fc  = (const float*)d_in[8];

    float* out    = (float*)d_out;
    float* hidden = out + HID_OFF;
    float* net    = out + NET_OFF;
    float* ro     = out + RO_OFF;

    // Pre-pass
    {
        dim3 g(B, T / 8);
        pre_kernel<<<g, 128>>>(input, sigma, noise, W_in, b_in, b_hh, net);
    }

    // Cluster recurrence (16 independent 8-CTA clusters)
    cudaFuncSetAttribute(rnn_cluster_kernel,
                         cudaFuncAttributeMaxDynamicSharedMemorySize, SMEM_BYTES);
    rnn_cluster_kernel<<<NCTA, NTHREADS, SMEM_BYTES>>>(W_hh, net);

    readout_kernel<<<(B * T) / 8, 256>>>(net, W_fc, b_fc, ro, out, hidden);
}

// round 12
// speedup vs baseline: 1.9296x; 1.9296x over previous
#include <cuda_runtime.h>
#include <cstdint>

// Problem constants
#define B 256
#define T 512
#define H 512
#define O 2

// d_out layout (floats): out, hidden, net_units, read_out_units
#define HID_OFF (B * O)
#define NET_OFF (HID_OFF + B * H)
#define RO_OFF  (NET_OFF + B * T * H)

#define NCTA     128          // 16 b-groups x 8 j-ranks
#define NTHREADS 512
#define HSTR     516          // hs row stride in floats (bank skew)

// smem: W2u[256 kp][64 ull colpairs] = 128 KB | hs[16][HSTR] | Rs[256] float4
#define W2_ULL     (256 * 64)
#define HS_FLOATS  (16 * HSTR)
#define SMEM_BYTES (W2_ULL * 8 + HS_FLOATS * 4 + 256 * 16)   // 168,192 B

// One monotonic flag per producer CTA, padded to 128B lines.
// flag[bg*8 + rank] (stride 32 u32). Producer stores t+1 after h(t) is in L2.
__device__ unsigned g_flag[16 * 8 * 32];

// ---------------------------------------------------------------------------
// Pre-pass: net[b,t,j] = input.W_in + b_in + b_hh + sigma*noise
// ---------------------------------------------------------------------------
__global__ __launch_bounds__(128) void pre_kernel(
    const float* __restrict__ input, const float* __restrict__ sigma,
    const float* __restrict__ noise, const float* __restrict__ W_in,
    const float* __restrict__ b_in,  const float* __restrict__ b_hh,
    float* __restrict__ net)
{
    const int b  = blockIdx.x;
    const int t0 = blockIdx.y * 8;
    const int j  = threadIdx.x * 4;

    float4 wi0 = *(const float4*)(W_in + j * 2);
    float4 wi1 = *(const float4*)(W_in + j * 2 + 4);
    float4 bi  = *(const float4*)(b_in + j);
    float4 bh  = *(const float4*)(b_hh + j);
    float4 c;
    c.x = bi.x + bh.x; c.y = bi.y + bh.y; c.z = bi.z + bh.z; c.w = bi.w + bh.w;
    const float sn = sigma[0];

    #pragma unroll
    for (int tt = 0; tt < 8; tt++) {
        const int t = t0 + tt;
        const size_t bt = (size_t)b * T + t;
        const float in0 = input[bt * 2 + 0];
        const float in1 = input[bt * 2 + 1];
        float4 nz = *(const float4*)(noise + bt * H + j);
        float4 r;
        r.x = in0 * wi0.x + in1 * wi0.y + c.x + sn * nz.x;
        r.y = in0 * wi0.z + in1 * wi0.w + c.y + sn * nz.y;
        r.z = in0 * wi1.x + in1 * wi1.y + c.z + sn * nz.z;
        r.w = in0 * wi1.z + in1 * wi1.w + c.w + sn * nz.w;
        *(float4*)(net + bt * H + j) = r;
    }
}

// ---------------------------------------------------------------------------
// Persistent recurrence. CTA: rank = bid & 7 (owns cols [64r,64r+64)),
// bg = bid >> 3 (owns batch rows [16bg, 16bg+16)).
// 512 threads: kh = tid>>8 (k-half), s = tid&255, row = s>>4, tc = s&15.
// Thread computes 4 cols (j0+4tc..+3) for row b0+row over its 256-k half.
// ---------------------------------------------------------------------------
__global__ __launch_bounds__(NTHREADS, 1) void rnn_persistent_kernel(
    const float* __restrict__ W_hh,   // [H,H]
    float*       __restrict__ net)    // [B,T,H]
{
    extern __shared__ unsigned char smemraw[];
    unsigned long long* W2u = (unsigned long long*)smemraw;            // k-pair W
    float*  hs = (float*)(smemraw + W2_ULL * 8);                       // h rows
    float4* Rs = (float4*)(smemraw + W2_ULL * 8 + HS_FLOATS * 4);      // partials

    const int tid  = threadIdx.x;
    const int rank = blockIdx.x & 7;
    const int bg   = blockIdx.x >> 3;
    const int b0   = bg * 16;
    const int j0   = rank * 64;

    const int kh    = tid >> 8;      // 0/1
    const int s     = tid & 255;
    const int row   = s >> 4;        // 0..15
    const int tc    = s & 15;        // cols j0 + 4tc .. +3
    const int ownkh = rank >> 2;     // which k-half contains own chunk

    unsigned* myflag = g_flag + (bg * 8 + rank) * 32;

    // ---- Load W tile once into k-pair layout:
    // W2u[kp*64 + pos(c)] = {W_hh[j0+c][2kp], W_hh[j0+c][2kp+1]}
    // pos(c) = (c&2 ? 32 : 0) + ((c>>2)<<1) + (c&1): thread tc's 4 cols sit at
    // ull offsets 2tc..2tc+1 and 32+2tc..+1 -> two 16B LDS per kp, conflict-free.
    {
        const int wc   = tid >> 3;            // 0..63
        const int wk0  = (tid & 7) * 64;
        const int posc = ((wc & 2) ? 32 : 0) + ((wc >> 2) << 1) + (wc & 1);
        const float* src = W_hh + (size_t)(j0 + wc) * H + wk0;
        float2* W2f = (float2*)W2u;
        #pragma unroll
        for (int c = 0; c < 64; c += 4) {
            float4 v = *(const float4*)(src + c);
            const int kp = (wk0 + c) >> 1;
            W2f[(kp + 0) * 64 + posc] = make_float2(v.x, v.y);
            W2f[(kp + 1) * 64 + posc] = make_float2(v.z, v.w);
        }
    }

    // ---- t = 0: h0 = relu(pre); store to net + own region of hs ----
    if (kh == 0) {
        float* dst = net + ((size_t)(b0 + row) * T + 0) * H + j0 + tc * 4;
        float4 p = __ldcg((const float4*)dst);
        p.x = fmaxf(p.x, 0.f); p.y = fmaxf(p.y, 0.f);
        p.z = fmaxf(p.z, 0.f); p.w = fmaxf(p.w, 0.f);
        *(float4*)dst = p;
        *(float4*)(hs + row * HSTR + j0 + tc * 4) = p;
    }
    __syncthreads();
    if (tid == 0)
        asm volatile("st.release.gpu.global.u32 [%0], %1;"
                     :: "l"(myflag), "r"(1u) : "memory");

    const float* hsrow = hs + row * HSTR;

#define ACCUM(KLO, KHI) do {                                                     \
    _Pragma("unroll 4")                                                          \
    for (int kp = (KLO); kp < (KHI); ++kp) {                                     \
        const unsigned long long hh =                                            \
            *(const unsigned long long*)(hsrow + 2 * kp);                        \
        const ulonglong2 q0 = *(const ulonglong2*)(W2u + kp * 64 + 2 * tc);      \
        const ulonglong2 q1 = *(const ulonglong2*)(W2u + kp * 64 + 32 + 2 * tc); \
        asm("fma.rn.f32x2 %0, %1, %2, %0;" : "+l"(a0) : "l"(hh), "l"(q0.x));     \
        asm("fma.rn.f32x2 %0, %1, %2, %0;" : "+l"(a1) : "l"(hh), "l"(q0.y));     \
        asm("fma.rn.f32x2 %0, %1, %2, %0;" : "+l"(a2) : "l"(hh), "l"(q1.x));     \
        asm("fma.rn.f32x2 %0, %1, %2, %0;" : "+l"(a3) : "l"(hh), "l"(q1.y));     \
    }                                                                            \
} while (0)

    for (int t = 1; t < T; t++) {
        // pre(t) prefetch: independent of peers, issue first
        float4 pre0;
        float* dst = nullptr;
        if (kh == 0) {
            dst  = net + ((size_t)(b0 + row) * T + t) * H + j0 + tc * 4;
            pre0 = __ldcg((const float4*)dst);
        }

        // ---- Pre-compute own k-chunk (data already in hs) while peers finish ----
        unsigned long long a0 = 0, a1 = 0, a2 = 0, a3 = 0;
        if (kh == ownkh) {
            const int olo = 32 * rank;
            ACCUM(olo, olo + 32);
        }

        // ---- Wait for the 7 peer producers (parallel acquire polls) ----
        if (tid >= 1 && tid < 8) {
            const unsigned* fp = g_flag + (bg * 8 + ((rank + tid) & 7)) * 32;
            unsigned v;
            do {
                asm volatile("ld.acquire.gpu.global.u32 %0, [%1];"
                             : "=r"(v) : "l"(fp) : "memory");
            } while (v < (unsigned)t);
        }
        __syncthreads();                       // [P] all h(t-1) visible

        // ---- Load h(t-1): 16 rows x 512 floats (2048 float4 / 512 threads) ----
        float4 v0, v1, v2, v3;
        {
            const int i0 = tid,        r0_ = i0 >> 7, q0_ = (i0 & 127) * 4;
            const int i1 = tid + 512,  r1_ = i1 >> 7, q1_ = (i1 & 127) * 4;
            const int i2 = tid + 1024, r2_ = i2 >> 7, q2_ = (i2 & 127) * 4;
            const int i3 = tid + 1536, r3_ = i3 >> 7, q3_ = (i3 & 127) * 4;
            const size_t tb = (size_t)(t - 1) * H;
            v0 = __ldcg((const float4*)(net + ((size_t)(b0 + r0_) * T) * H + tb + q0_));
            v1 = __ldcg((const float4*)(net + ((size_t)(b0 + r1_) * T) * H + tb + q1_));
            v2 = __ldcg((const float4*)(net + ((size_t)(b0 + r2_) * T) * H + tb + q2_));
            v3 = __ldcg((const float4*)(net + ((size_t)(b0 + r3_) * T) * H + tb + q3_));
            *(float4*)(hs + r0_ * HSTR + q0_) = v0;
            *(float4*)(hs + r1_ * HSTR + q1_) = v1;
            *(float4*)(hs + r2_ * HSTR + q2_) = v2;
            *(float4*)(hs + r3_ * HSTR + q3_) = v3;
        }
        __syncthreads();                       // [S] h tile staged

        // ---- Remaining k of this thread's half (skip own chunk if in it) ----
        {
            const int klo = 128 * kh, khi = klo + 128;
            if (kh == ownkh) {
                const int olo = 32 * rank;
                ACCUM(klo, olo);
                ACCUM(olo + 32, khi);
            } else {
                ACCUM(klo, khi);
            }
        }

        // combine the even/odd-k halves of each f32x2
        float f0, f1, f2, f3, lo, hi;
        asm("mov.b64 {%0,%1}, %2;" : "=f"(lo), "=f"(hi) : "l"(a0)); f0 = lo + hi;
        asm("mov.b64 {%0,%1}, %2;" : "=f"(lo), "=f"(hi) : "l"(a1)); f1 = lo + hi;
        asm("mov.b64 {%0,%1}, %2;" : "=f"(lo), "=f"(hi) : "l"(a2)); f2 = lo + hi;
        asm("mov.b64 {%0,%1}, %2;" : "=f"(lo), "=f"(hi) : "l"(a3)); f3 = lo + hi;

        if (kh == 1) Rs[s] = make_float4(f0, f1, f2, f3);
        __syncthreads();                       // [R] partials staged

        if (kh == 0) {
            float4 p = Rs[s];
            float4 o;
            o.x = fmaxf(f0 + p.x + pre0.x, 0.f);
            o.y = fmaxf(f1 + p.y + pre0.y, 0.f);
            o.z = fmaxf(f2 + p.z + pre0.z, 0.f);
            o.w = fmaxf(f3 + p.w + pre0.w, 0.f);
            *(float4*)dst = o;                                   // h(t) -> net
            *(float4*)(hs + row * HSTR + j0 + tc * 4) = o;       // own region
        }
        __syncthreads();                       // [E] stores done (net + hs-own)

        if (tid == 0)
            asm volatile("st.release.gpu.global.u32 [%0], %1;"
                         :: "l"(myflag), "r"((unsigned)(t + 1)) : "memory");
    }
#undef ACCUM
}

// ---------------------------------------------------------------------------
// Readout: ro[b,t,o] = net[b,t,:].W_fc[o,:] + b_fc[o]; out/hidden from t=T-1
// ---------------------------------------------------------------------------
__global__ __launch_bounds__(256) void readout_kernel(
    const float* __restrict__ net, const float* __restrict__ W_fc,
    const float* __restrict__ b_fc, float* __restrict__ ro,
    float* __restrict__ out, float* __restrict__ hidden)
{
    __shared__ float4 w0s[H / 4];
    __shared__ float4 w1s[H / 4];
    const int tid = threadIdx.x;
    if (tid < H / 4)            w0s[tid]         = ((const float4*)W_fc)[tid];
    else if (tid < 2 * (H / 4)) w1s[tid - H / 4] = ((const float4*)(W_fc + H))[tid - H / 4];
    __syncthreads();

    const int warp = tid >> 5, lane = tid & 31;
    const int bt = blockIdx.x * 8 + warp;
    const int b = bt / T, t = bt % T;

    const float4* rowp = (const float4*)(net + (size_t)bt * H);
    float a0 = 0.f, a1 = 0.f;
    float4 vals[4];
    #pragma unroll
    for (int i = 0; i < 4; i++) {
        float4 v  = rowp[lane + 32 * i];
        float4 w0 = w0s[lane + 32 * i];
        float4 w1 = w1s[lane + 32 * i];
        vals[i] = v;
        a0 += v.x * w0.x + v.y * w0.y + v.z * w0.z + v.w * w0.w;
        a1 += v.x * w1.x + v.y * w1.y + v.z * w1.z + v.w * w1.w;
    }
    #pragma unroll
    for (int sg = 16; sg > 0; sg >>= 1) {
        a0 += __shfl_xor_sync(0xFFFFFFFFu, a0, sg);
        a1 += __shfl_xor_sync(0xFFFFFFFFu, a1, sg);
    }
    if (lane == 0) {
        ro[(size_t)bt * 2 + 0] = a0 + b_fc[0];
        ro[(size_t)bt * 2 + 1] = a1 + b_fc[1];
    }
    if (t == T - 1) {
        if (lane == 0) {
            out[b * 2 + 0] = a0 + b_fc[0];
            out[b * 2 + 1] = a1 + b_fc[1];
        }
        float4* hid = (float4*)(hidden + (size_t)b * H);
        #pragma unroll
        for (int i = 0; i < 4; i++) hid[lane + 32 * i] = vals[i];
    }
}

extern "C" void kernel_launch(void* const* d_in, const int* in_sizes, int n_in,
                              void* d_out, int out_size)
{
    const float* input = (const float*)d_in[0];
    const float* sigma = (const float*)d_in[1];
    const float* noise = (const float*)d_in[2];
    const float* W_in  = (const float*)d_in[3];
    const float* b_in  = (const float*)d_in[4];
    const float* W_hh  = (const float*)d_in[5];
    const float* b_hh  = (const float*)d_in[6];
    const float* W_fc  = (const float*)d_in[7];
    const float* b_fc  = (const float*)d_in[8];

    float* out    = (float*)d_out;
    float* hidden = out + HID_OFF;
    float* net    = out + NET_OFF;
    float* ro     = out + RO_OFF;

    // Reset producer flags (graph-capturable)
    void* flag_ptr = nullptr;
    cudaGetSymbolAddress(&flag_ptr, g_flag);
    cudaMemsetAsync(flag_ptr, 0, 16 * 8 * 32 * sizeof(unsigned), 0);

    // Pre-pass
    {
        dim3 g(B, T / 8);
        pre_kernel<<<g, 128>>>(input, sigma, noise, W_in, b_in, b_hh, net);
    }

    // Persistent recurrence
    cudaFuncSetAttribute(rnn_persistent_kernel,
                         cudaFuncAttributeMaxDynamicSharedMemorySize, SMEM_BYTES);
    rnn_persistent_kernel<<<NCTA, NTHREADS, SMEM_BYTES>>>(W_hh, net);

    readout_kernel<<<(B * T) / 8, 256>>>(net, W_fc, b_fc, ro, out, hidden);
}